// round 15
// baseline (speedup 1.0000x reference)
#include <cuda_runtime.h>

#define T_STEPS 512
#define BATCH   64
#define HID     512
#define GATES3  1536
#define NB_REC  128
#define NT_REC  256
#define WROW8   1064   // W row stride (8 eighths x 132 + pad 8)
#define WKOFF   132    // W k-eighth stride (128 floats [64k x 2cols] + pad 4)
#define HROW8   544    // h row stride (8 eighths x 68)
#define HKOFF   68     // h k-eighth stride (64 + pad 4)

// ---------------- scratch (static device allocations; no cudaMalloc) ----------------
__device__ float g_xg[(size_t)T_STEPS * BATCH * GATES3]; // precomputed input gates
__device__ float g_y0[(size_t)T_STEPS * BATCH * HID];    // layer-0 output
__device__ float g_hx[2 * BATCH * HID];                  // ping-pong h exchange [parity][b][j]
__device__ unsigned g_flags[NB_REC];                     // per-block step flags
__device__ unsigned g_end_cnt[8];
__device__ volatile unsigned g_end_gen[8];

// ---------------- packed fp32x2 FMA (Blackwell FFMA2) ----------------
__device__ __forceinline__ float2 ffma2(float2 a, float2 b, float2 c) {
    float2 d;
    asm("fma.rn.f32x2 %0, %1, %2, %3;"
        : "=l"(reinterpret_cast<unsigned long long&>(d))
        : "l"(reinterpret_cast<unsigned long long&>(a)),
          "l"(reinterpret_cast<unsigned long long&>(b)),
          "l"(reinterpret_cast<unsigned long long&>(c)));
    return d;
}

__device__ __forceinline__ float fast_sigmoid(float x) {
    return __fdividef(1.f, 1.f + __expf(-x));
}
__device__ __forceinline__ float fast_tanh(float x) {
    float r;
    asm("tanh.approx.f32 %0, %1;" : "=f"(r) : "f"(x));
    return r;
}
__device__ __forceinline__ float2 shfl_xor_f2(float2 v, int m) {
    v.x = __shfl_xor_sync(0xffffffffu, v.x, m);
    v.y = __shfl_xor_sync(0xffffffffu, v.y, m);
    return v;
}
__device__ __forceinline__ float2 add_f2(float2 a, float2 b) {
    return make_float2(a.x + b.x, a.y + b.y);
}

// ---------------- GEMM: out[M,N] = A[M,K] * W[N,K]^T + bias (R2 version, known-good) ----
__global__ void __launch_bounds__(256) gemm_bias_kernel(
    const float* __restrict__ A, const float* __restrict__ W,
    const float* __restrict__ bias, float* __restrict__ out, int K)
{
    __shared__ float As[16 * 132];
    __shared__ float Bs[16 * 132];

    const int tid = threadIdx.x;
    const int m0 = blockIdx.y * 128;
    const int n0 = blockIdx.x * 128;
    const int tm = tid >> 4;
    const int tn = tid & 15;

    float2 c2[8][4];
#pragma unroll
    for (int i = 0; i < 8; ++i)
#pragma unroll
        for (int p = 0; p < 4; ++p) c2[i][p] = make_float2(0.f, 0.f);

    for (int kt = 0; kt < K; kt += 16) {
#pragma unroll
        for (int u = 0; u < 2; ++u) {
            int s   = tid + u * 256;
            int row = s >> 2;
            int c4  = s & 3;
            float4 av = *(const float4*)(A + (size_t)(m0 + row) * K + kt + c4 * 4);
            As[(c4 * 4 + 0) * 132 + row] = av.x;
            As[(c4 * 4 + 1) * 132 + row] = av.y;
            As[(c4 * 4 + 2) * 132 + row] = av.z;
            As[(c4 * 4 + 3) * 132 + row] = av.w;
            float4 bv = *(const float4*)(W + (size_t)(n0 + row) * K + kt + c4 * 4);
            Bs[(c4 * 4 + 0) * 132 + row] = bv.x;
            Bs[(c4 * 4 + 1) * 132 + row] = bv.y;
            Bs[(c4 * 4 + 2) * 132 + row] = bv.z;
            Bs[(c4 * 4 + 3) * 132 + row] = bv.w;
        }
        __syncthreads();

#pragma unroll
        for (int kb = 0; kb < 16; ++kb) {
            float4 a0 = *(const float4*)(As + kb * 132 + tm * 8);
            float4 a1 = *(const float4*)(As + kb * 132 + tm * 8 + 4);
            float4 b0 = *(const float4*)(Bs + kb * 132 + tn * 8);
            float4 b1 = *(const float4*)(Bs + kb * 132 + tn * 8 + 4);
            float av[8] = {a0.x, a0.y, a0.z, a0.w, a1.x, a1.y, a1.z, a1.w};
            float2 bp[4] = {make_float2(b0.x, b0.y), make_float2(b0.z, b0.w),
                            make_float2(b1.x, b1.y), make_float2(b1.z, b1.w)};
#pragma unroll
            for (int i = 0; i < 8; ++i) {
                float2 as = make_float2(av[i], av[i]);
#pragma unroll
                for (int p = 0; p < 4; ++p) c2[i][p] = ffma2(as, bp[p], c2[i][p]);
            }
        }
        __syncthreads();
    }

    const float4 bb0 = *(const float4*)(bias + n0 + tn * 8);
    const float4 bb1 = *(const float4*)(bias + n0 + tn * 8 + 4);
#pragma unroll
    for (int i = 0; i < 8; ++i) {
        int m = m0 + tm * 8 + i;
        float4 o0 = make_float4(c2[i][0].x + bb0.x, c2[i][0].y + bb0.y,
                                c2[i][1].x + bb0.z, c2[i][1].y + bb0.w);
        float4 o1 = make_float4(c2[i][2].x + bb1.x, c2[i][2].y + bb1.y,
                                c2[i][3].x + bb1.z, c2[i][3].y + bb1.w);
        float* dst = out + (size_t)m * GATES3 + n0 + tn * 8;
        *(float4*)(dst)     = o0;
        *(float4*)(dst + 4) = o1;
    }
}

// ---------------- persistent GRU recurrence ----------------
// 128 blocks = 16 col-groups x 8 batch-groups. 256 threads: tid = cp*16 + bh*8 + kk
// (cp: 16 col-pairs, bh: 2 batch-halves, kk: 8 k-eighths).
// Thread: 2 cols x 3 gates x 4 batches x K=64. 1280 LDS.128/block/step; 2 warps/SMSP.
// k-reduction: reduce-scatter (xor4, xor2) + allreduce (xor1): 24 SHFL.
// After reduction thread kk holds batch lb = kk>>1 (even/odd kk duplicate);
// even-kk threads finalize + store batch b0 + bh*4 + (kk>>1).
__global__ void __launch_bounds__(NT_REC, 1) gru_rec_kernel(
    const float* __restrict__ xg, const float* __restrict__ Whh,
    const float* __restrict__ bhh, float* __restrict__ y,
    float* __restrict__ hn_out)
{
    extern __shared__ float smem[];
    float* Ws = smem;                  // 48 rows (g*16+cp) x 1064 (col-pair interleaved, k-eighths)
    float* hs = smem + 48 * WROW8;     // 8 rows (batch) x 544 (k-eighths, stride 68)

    const int tid = threadIdx.x;
    const int bid = blockIdx.x;
    const int cg  = bid & 15;
    const int grp = bid >> 4;
    const int j0  = cg * 32;
    const int b0  = grp * 8;
    const int cp  = tid >> 4;          // 0..15
    const int bh  = (tid >> 3) & 1;    // 0..1 batch half
    const int kk  = tid & 7;           // 0..7 k-eighth
    const int jj  = j0 + cp * 2;
    const int lb  = bh * 4 + (kk >> 1);   // local batch this thread finalizes (even kk)
    const int b   = b0 + lb;
    const bool fin = ((kk & 1) == 0);

    // one-time: W_hh slice, col-pair interleaved + k-eighth split:
    // Ws[(g*16+cp)*1064 + (k>>6)*132 + (k&63)*2 + c] = Whh[g*512 + j0+2cp+c][k]
    for (int idx = tid; idx < 96 * 512; idx += NT_REC) {
        int row = idx >> 9;            // g*32 + cc
        int k   = idx & 511;
        int g   = row >> 5;
        int cc  = row & 31;
        Ws[(g * 16 + (cc >> 1)) * WROW8 + (k >> 6) * WKOFF + (k & 63) * 2 + (cc & 1)] =
            Whh[(size_t)(g * HID + j0 + cc) * HID + k];
    }
    for (int idx = tid; idx < 8 * HROW8; idx += NT_REC) hs[idx] = 0.f;

    const float2 bhr = *(const float2*)(bhh + jj);
    const float2 bhz = *(const float2*)(bhh + HID + jj);
    const float2 bhn = *(const float2*)(bhh + 2 * HID + jj);

    const float* wr = Ws + cp * WROW8 + kk * WKOFF;
    const float* wz = wr + 16 * WROW8;
    const float* wn = wr + 32 * WROW8;
    const float* hb = hs + (bh * 4) * HROW8 + kk * HKOFF;   // 4 rows starting at bh*4

    const size_t xofs = (size_t)b * GATES3 + jj;
    float2 xr = {0,0}, xz = {0,0}, xn = {0,0};
    if (fin) {
        xr = *(const float2*)(xg + xofs);
        xz = *(const float2*)(xg + xofs + HID);
        xn = *(const float2*)(xg + xofs + 2 * HID);
    }

    float2 hp = make_float2(0.f, 0.f);   // own h (2 cols of batch b), even-kk threads
    __syncthreads();

    for (int t = 0; t < T_STEPS; ++t) {
        if (t > 0) {
            if (tid < 16 && tid != cg) {
                const unsigned* fp = &g_flags[grp * 16 + tid];
                unsigned v;
                do {
                    asm volatile("ld.acquire.gpu.global.u32 %0, [%1];" : "=r"(v) : "l"(fp));
                } while (v < (unsigned)t);
            }
            __syncthreads();
            // stage remote h: 1024 float4 over 256 threads, skip own col-block
            const float* hsrc = g_hx + (size_t)(t & 1) * BATCH * HID;
#pragma unroll
            for (int i = 0; i < 4; ++i) {
                int idx = tid + i * NT_REC;
                int bb  = idx >> 7;            // 0..7
                int kq  = idx & 127;           // float4 quarter of 512
                if ((kq >> 3) != cg) {
                    float4 hv = __ldcg((const float4*)(hsrc + (size_t)(b0 + bb) * HID + kq * 4));
                    *(float4*)(hs + bb * HROW8 + (kq >> 4) * HKOFF + (kq & 15) * 4) = hv;
                }
            }
            __syncthreads();
        }

        // prefetch next step's xg (hides under the dot)
        float2 nxr = {0,0}, nxz = {0,0}, nxn = {0,0};
        if (fin && t + 1 < T_STEPS) {
            const float* xp = xg + (size_t)(t + 1) * BATCH * GATES3 + xofs;
            nxr = *(const float2*)(xp);
            nxz = *(const float2*)(xp + HID);
            nxn = *(const float2*)(xp + 2 * HID);
        }

        // K=64 dot: 3 gates x 2 cols (FFMA2-packed) x 4 batches
        float2 ar[4], az[4], an[4];
#pragma unroll
        for (int i = 0; i < 4; ++i) { ar[i] = make_float2(0,0); az[i] = ar[i]; an[i] = ar[i]; }

#pragma unroll 2
        for (int k = 0; k < 64; k += 4) {
            float4 r01 = *(const float4*)(wr + k * 2);
            float4 r23 = *(const float4*)(wr + k * 2 + 4);
            float4 z01 = *(const float4*)(wz + k * 2);
            float4 z23 = *(const float4*)(wz + k * 2 + 4);
            float4 n01 = *(const float4*)(wn + k * 2);
            float4 n23 = *(const float4*)(wn + k * 2 + 4);
            float2 wr0 = make_float2(r01.x, r01.y), wr1 = make_float2(r01.z, r01.w);
            float2 wr2 = make_float2(r23.x, r23.y), wr3 = make_float2(r23.z, r23.w);
            float2 wz0 = make_float2(z01.x, z01.y), wz1 = make_float2(z01.z, z01.w);
            float2 wz2 = make_float2(z23.x, z23.y), wz3 = make_float2(z23.z, z23.w);
            float2 wn0 = make_float2(n01.x, n01.y), wn1 = make_float2(n01.z, n01.w);
            float2 wn2 = make_float2(n23.x, n23.y), wn3 = make_float2(n23.z, n23.w);
#pragma unroll
            for (int bb = 0; bb < 4; ++bb) {
                float4 hv = *(const float4*)(hb + bb * HROW8 + k);
                float2 hx = make_float2(hv.x, hv.x);
                float2 hy = make_float2(hv.y, hv.y);
                float2 hzv = make_float2(hv.z, hv.z);
                float2 hw = make_float2(hv.w, hv.w);
                ar[bb] = ffma2(wr0, hx, ar[bb]);
                ar[bb] = ffma2(wr1, hy, ar[bb]);
                ar[bb] = ffma2(wr2, hzv, ar[bb]);
                ar[bb] = ffma2(wr3, hw, ar[bb]);
                az[bb] = ffma2(wz0, hx, az[bb]);
                az[bb] = ffma2(wz1, hy, az[bb]);
                az[bb] = ffma2(wz2, hzv, az[bb]);
                az[bb] = ffma2(wz3, hw, az[bb]);
                an[bb] = ffma2(wn0, hx, an[bb]);
                an[bb] = ffma2(wn1, hy, an[bb]);
                an[bb] = ffma2(wn2, hzv, an[bb]);
                an[bb] = ffma2(wn3, hw, an[bb]);
            }
        }

        // Round 1 (xor 4): combine k across kk bit2; keep batch pair {0,1} or {2,3}
#pragma unroll
        for (int i = 0; i < 2; ++i) {
            float2 s;
            s = (kk & 4) ? ar[i] : ar[i + 2]; s = shfl_xor_f2(s, 4);
            ar[i] = add_f2((kk & 4) ? ar[i + 2] : ar[i], s);
            s = (kk & 4) ? az[i] : az[i + 2]; s = shfl_xor_f2(s, 4);
            az[i] = add_f2((kk & 4) ? az[i + 2] : az[i], s);
            s = (kk & 4) ? an[i] : an[i + 2]; s = shfl_xor_f2(s, 4);
            an[i] = add_f2((kk & 4) ? an[i + 2] : an[i], s);
        }
        // Round 2 (xor 2): keep single batch lb = kk>>1
        {
            float2 s;
            s = (kk & 2) ? ar[0] : ar[1]; s = shfl_xor_f2(s, 2);
            ar[0] = add_f2((kk & 2) ? ar[1] : ar[0], s);
            s = (kk & 2) ? az[0] : az[1]; s = shfl_xor_f2(s, 2);
            az[0] = add_f2((kk & 2) ? az[1] : az[0], s);
            s = (kk & 2) ? an[0] : an[1]; s = shfl_xor_f2(s, 2);
            an[0] = add_f2((kk & 2) ? an[1] : an[0], s);
        }
        // Round 3 (xor 1): allreduce last k-halves (kk and kk^1 share lb)
        ar[0] = add_f2(ar[0], shfl_xor_f2(ar[0], 1));
        az[0] = add_f2(az[0], shfl_xor_f2(az[0], 1));
        an[0] = add_f2(an[0], shfl_xor_f2(an[0], 1));

        if (fin) {
            // finalize batch b, cols jj..jj+1
            float rX = fast_sigmoid(xr.x + ar[0].x + bhr.x);
            float rY = fast_sigmoid(xr.y + ar[0].y + bhr.y);
            float zX = fast_sigmoid(xz.x + az[0].x + bhz.x);
            float zY = fast_sigmoid(xz.y + az[0].y + bhz.y);
            float nX = fast_tanh(xn.x + rX * (an[0].x + bhn.x));
            float nY = fast_tanh(xn.y + rY * (an[0].y + bhn.y));
            hp.x = (1.f - zX) * nX + zX * hp.x;
            hp.y = (1.f - zY) * nY + zY * hp.y;

            // publish h to L2 FIRST (critical path for remote blocks)
            float* hdst = g_hx + (size_t)((t + 1) & 1) * BATCH * HID + (size_t)b * HID + jj;
            asm volatile("st.global.cg.v2.f32 [%0], {%1, %2};"
                         :: "l"(hdst), "f"(hp.x), "f"(hp.y) : "memory");
        }
        __syncthreads();
        if (tid == 0 && t < T_STEPS - 1) {
            __threadfence();
            asm volatile("st.global.cg.u32 [%0], %1;"
                         :: "l"(&g_flags[bid]), "r"((unsigned)(t + 1)) : "memory");
        }

        if (fin) {
            // own-slice shortcut into smem (post-sync: safe vs this step's reads)
            *(float2*)(hs + lb * HROW8 + (jj >> 6) * HKOFF + (jj & 63)) = hp;

            // off critical path: y store, hn store
            *(float2*)(y + ((size_t)t * BATCH + b) * HID + jj) = hp;
            if (t == T_STEPS - 1) *(float2*)(hn_out + (size_t)b * HID + jj) = hp;

            xr = nxr; xz = nxz; xn = nxn;
        }
    }

    // end-of-launch: group gen-barrier (replay-safe), reset own flag
    __syncthreads();
    if (tid == 0) {
        unsigned gen = g_end_gen[grp];
        __threadfence();
        if (atomicAdd(&g_end_cnt[grp], 1u) == 15u) {
            g_end_cnt[grp] = 0u;
            __threadfence();
            g_end_gen[grp] = gen + 1u;
        } else {
            while (g_end_gen[grp] == gen) { __nanosleep(32); }
        }
        g_flags[bid] = 0u;
        __threadfence();
    }
}

// ---------------- launch ----------------
extern "C" void kernel_launch(void* const* d_in, const int* in_sizes, int n_in,
                              void* d_out, int out_size) {
    const float* x    = (const float*)d_in[0];
    const float* Wih0 = (const float*)d_in[1];
    const float* Whh0 = (const float*)d_in[2];
    const float* bih0 = (const float*)d_in[3];
    const float* bhh0 = (const float*)d_in[4];
    const float* Wih1 = (const float*)d_in[5];
    const float* Whh1 = (const float*)d_in[6];
    const float* bih1 = (const float*)d_in[7];
    const float* bhh1 = (const float*)d_in[8];

    float* out = (float*)d_out;
    float* y1  = out;
    float* hn0 = out + (size_t)T_STEPS * BATCH * HID;
    float* hn1 = hn0 + BATCH * HID;

    float *xg, *y0;
    cudaGetSymbolAddress((void**)&xg, g_xg);
    cudaGetSymbolAddress((void**)&y0, g_y0);

    const int rec_smem = (48 * WROW8 + 8 * HROW8) * 4;  // 221,696 B
    cudaFuncSetAttribute(gru_rec_kernel, cudaFuncAttributeMaxDynamicSharedMemorySize, rec_smem);

    dim3 ggrid(12, 256);

    gemm_bias_kernel<<<ggrid, 256>>>(x, Wih0, bih0, xg, 256);
    gru_rec_kernel<<<NB_REC, NT_REC, rec_smem>>>(xg, Whh0, bhh0, y0, hn0);
    gemm_bias_kernel<<<ggrid, 256>>>(y0, Wih1, bih1, xg, 512);
    gru_rec_kernel<<<NB_REC, NT_REC, rec_smem>>>(xg, Whh1, bhh1, y1, hn1);
}

// round 16
// speedup vs baseline: 1.2153x; 1.2153x over previous
#include <cuda_runtime.h>

#define T_STEPS 512
#define BATCH   64
#define HID     512
#define GATES3  1536
#define NB_REC  128
#define NT_REC  128
#define WROWF   1040   // W row stride in floats (2*520; k-half offset 520, 16B-aligned)
#define KHOFF   520    // k-half offset within a W row
#define HR      516    // h row stride in floats (k-half offset 260)

// ---------------- scratch (static device allocations; no cudaMalloc) ----------------
__device__ float g_xg[(size_t)T_STEPS * BATCH * GATES3]; // precomputed input gates
__device__ float g_y0[(size_t)T_STEPS * BATCH * HID];    // layer-0 output
__device__ float g_hx[2 * BATCH * HID];                  // ping-pong h exchange [parity][b][j]
__device__ unsigned g_flags[NB_REC];                     // per-block step flags
__device__ unsigned g_end_cnt[8];
__device__ volatile unsigned g_end_gen[8];

// ---------------- packed fp32x2 FMA (Blackwell FFMA2) ----------------
__device__ __forceinline__ float2 ffma2(float2 a, float2 b, float2 c) {
    float2 d;
    asm("fma.rn.f32x2 %0, %1, %2, %3;"
        : "=l"(reinterpret_cast<unsigned long long&>(d))
        : "l"(reinterpret_cast<unsigned long long&>(a)),
          "l"(reinterpret_cast<unsigned long long&>(b)),
          "l"(reinterpret_cast<unsigned long long&>(c)));
    return d;
}

__device__ __forceinline__ float fast_sigmoid(float x) {
    return __fdividef(1.f, 1.f + __expf(-x));
}
__device__ __forceinline__ float fast_tanh(float x) {
    float r;
    asm("tanh.approx.f32 %0, %1;" : "=f"(r) : "f"(x));
    return r;
}

// ---------------- GEMM: out[M,N] = A[M,K] * W[N,K]^T + bias ----------------
// 128x128 tile, BK=32 (half the syncs, 2x gmem MLP vs BK=16), 256 threads.
__global__ void __launch_bounds__(256) gemm_bias_kernel(
    const float* __restrict__ A, const float* __restrict__ W,
    const float* __restrict__ bias, float* __restrict__ out, int K)
{
    __shared__ float As[32 * 132];
    __shared__ float Bs[32 * 132];

    const int tid = threadIdx.x;
    const int m0 = blockIdx.y * 128;
    const int n0 = blockIdx.x * 128;
    const int tm = tid >> 4;
    const int tn = tid & 15;

    float2 c2[8][4];
#pragma unroll
    for (int i = 0; i < 8; ++i)
#pragma unroll
        for (int p = 0; p < 4; ++p) c2[i][p] = make_float2(0.f, 0.f);

    for (int kt = 0; kt < K; kt += 32) {
        // stage 128x32 of A and W: 1024 float4 each over 256 threads (4+4 per thread)
#pragma unroll
        for (int u = 0; u < 4; ++u) {
            int f   = tid + u * 256;      // 0..1023
            int row = f >> 3;             // 0..127
            int c4  = f & 7;              // k-float4 0..7
            float4 av = *(const float4*)(A + (size_t)(m0 + row) * K + kt + c4 * 4);
            As[(c4 * 4 + 0) * 132 + row] = av.x;
            As[(c4 * 4 + 1) * 132 + row] = av.y;
            As[(c4 * 4 + 2) * 132 + row] = av.z;
            As[(c4 * 4 + 3) * 132 + row] = av.w;
            float4 bv = *(const float4*)(W + (size_t)(n0 + row) * K + kt + c4 * 4);
            Bs[(c4 * 4 + 0) * 132 + row] = bv.x;
            Bs[(c4 * 4 + 1) * 132 + row] = bv.y;
            Bs[(c4 * 4 + 2) * 132 + row] = bv.z;
            Bs[(c4 * 4 + 3) * 132 + row] = bv.w;
        }
        __syncthreads();

#pragma unroll
        for (int kb = 0; kb < 32; ++kb) {
            float4 a0 = *(const float4*)(As + kb * 132 + tm * 8);
            float4 a1 = *(const float4*)(As + kb * 132 + tm * 8 + 4);
            float4 b0 = *(const float4*)(Bs + kb * 132 + tn * 8);
            float4 b1 = *(const float4*)(Bs + kb * 132 + tn * 8 + 4);
            float av[8] = {a0.x, a0.y, a0.z, a0.w, a1.x, a1.y, a1.z, a1.w};
            float2 bp[4] = {make_float2(b0.x, b0.y), make_float2(b0.z, b0.w),
                            make_float2(b1.x, b1.y), make_float2(b1.z, b1.w)};
#pragma unroll
            for (int i = 0; i < 8; ++i) {
                float2 as = make_float2(av[i], av[i]);
#pragma unroll
                for (int p = 0; p < 4; ++p) c2[i][p] = ffma2(as, bp[p], c2[i][p]);
            }
        }
        __syncthreads();
    }

    const float4 bb0 = *(const float4*)(bias + n0 + tn * 8);
    const float4 bb1 = *(const float4*)(bias + n0 + tn * 8 + 4);
#pragma unroll
    for (int i = 0; i < 8; ++i) {
        int m = m0 + tm * 8 + i;
        float4 o0 = make_float4(c2[i][0].x + bb0.x, c2[i][0].y + bb0.y,
                                c2[i][1].x + bb0.z, c2[i][1].y + bb0.w);
        float4 o1 = make_float4(c2[i][2].x + bb1.x, c2[i][2].y + bb1.y,
                                c2[i][3].x + bb1.z, c2[i][3].y + bb1.w);
        float* dst = out + (size_t)m * GATES3 + n0 + tn * 8;
        *(float4*)(dst)     = o0;
        *(float4*)(dst + 4) = o1;
    }
}

// ---------------- persistent GRU recurrence (R13 champion, byte-identical) ----------
// 128 blocks = 16 col-groups x 8 batch-groups. 128 threads:
// tid = cp*8 + bq*2 + kk  (cp: 16 col-pairs, bq: 4 batch-pairs, kk: k-half).
// Thread tile: 2 cols x 3 gates x 2 batches x K=256. k-reduction = __shfl_xor(1).
__global__ void __launch_bounds__(NT_REC, 1) gru_rec_kernel(
    const float* __restrict__ xg, const float* __restrict__ Whh,
    const float* __restrict__ bhh, float* __restrict__ y,
    float* __restrict__ hn_out)
{
    extern __shared__ float smem[];
    float* Ws = smem;                  // 48 rows (g*16+cp) x 1040 floats (col-pair interleaved)
    float* hs = smem + 48 * WROWF;     // 8 rows (batch) x 516 floats (k-half at +260)

    const int tid = threadIdx.x;
    const int bid = blockIdx.x;
    const int cg  = bid & 15;
    const int grp = bid >> 4;
    const int j0  = cg * 32;
    const int b0  = grp * 8;
    const int cp  = tid >> 3;          // 0..15
    const int bq  = (tid >> 1) & 3;    // 0..3
    const int kk  = tid & 1;           // 0..1
    const int jj  = j0 + cp * 2;       // first of this thread's col pair
    const int bA  = b0 + bq * 2;       // first of this thread's batch pair
    const int bB  = bA + 1;

    // one-time: W_hh slice, col-pair interleaved + k-half split:
    // Ws[(g*16+cp)*1040 + kh*520 + kl*2 + c] = Whh[g*512 + j0+2cp+c][kh*256+kl]
    for (int idx = tid; idx < 96 * 512; idx += NT_REC) {
        int row = idx >> 9;            // g*32 + cc
        int k   = idx & 511;
        int g   = row >> 5;
        int cc  = row & 31;
        int cpp = cc >> 1;
        int c   = cc & 1;
        int kh  = k >> 8;
        int kl  = k & 255;
        Ws[(g * 16 + cpp) * WROWF + kh * KHOFF + kl * 2 + c] =
            Whh[(size_t)(g * HID + j0 + cc) * HID + k];
    }
    for (int idx = tid; idx < 8 * HR; idx += NT_REC) hs[idx] = 0.f;

    // biases for this thread's col pair (only kk==0 finalizes)
    const float2 bhr = *(const float2*)(bhh + jj);
    const float2 bhz = *(const float2*)(bhh + HID + jj);
    const float2 bhn = *(const float2*)(bhh + 2 * HID + jj);

    const float* wr = Ws + cp * WROWF + kk * KHOFF;
    const float* wz = wr + 16 * WROWF;
    const float* wn = wr + 32 * WROWF;
    const float* h0p = hs + (bq * 2) * HR + kk * 260;
    const float* h1p = h0p + HR;

    // xg offsets (kk==0 threads only; 2 batches x 3 gates x col-pair)
    const size_t xoA = (size_t)bA * GATES3 + jj;
    const size_t xoB = (size_t)bB * GATES3 + jj;
    float2 xrA = {0,0}, xzA = {0,0}, xnA = {0,0};
    float2 xrB = {0,0}, xzB = {0,0}, xnB = {0,0};
    if (kk == 0) {
        xrA = *(const float2*)(xg + xoA);
        xzA = *(const float2*)(xg + xoA + HID);
        xnA = *(const float2*)(xg + xoA + 2 * HID);
        xrB = *(const float2*)(xg + xoB);
        xzB = *(const float2*)(xg + xoB + HID);
        xnB = *(const float2*)(xg + xoB + 2 * HID);
    }

    // own h (col pair x 2 batches), kept in kk==0 regs
    float2 hpA = {0,0}, hpB = {0,0};

    // own-slice smem offset for col j: +4 if j >= 256 (k-half layout)
    const int own_off = jj + ((cg >= 8) ? 4 : 0);
    __syncthreads();

    for (int t = 0; t < T_STEPS; ++t) {
        if (t > 0) {
            if (tid < 16 && tid != cg) {
                const unsigned* fp = &g_flags[grp * 16 + tid];
                unsigned v;
                do {
                    asm volatile("ld.acquire.gpu.global.u32 %0, [%1];" : "=r"(v) : "l"(fp));
                } while (v < (unsigned)t);
            }
            __syncthreads();
            // stage remote h: 1024 float4 over 128 threads, skip own col-block
            const float* hsrc = g_hx + (size_t)(t & 1) * BATCH * HID;
#pragma unroll
            for (int i = 0; i < 8; ++i) {
                int idx = tid + i * NT_REC;
                int bb  = idx >> 7;            // 0..7
                int kq  = idx & 127;           // float4 quarter
                if ((kq >> 3) != cg) {
                    float4 hv = __ldcg((const float4*)(hsrc + (size_t)(b0 + bb) * HID + kq * 4));
                    *(float4*)(hs + bb * HR + ((kq >= 64) ? 4 : 0) + kq * 4) = hv;
                }
            }
            __syncthreads();
        }

        // prefetch next step's xg (kk==0 only; hides under the dot)
        float2 nxrA = {0,0}, nxzA = {0,0}, nxnA = {0,0};
        float2 nxrB = {0,0}, nxzB = {0,0}, nxnB = {0,0};
        if (kk == 0 && t + 1 < T_STEPS) {
            const float* xpA = xg + (size_t)(t + 1) * BATCH * GATES3 + xoA;
            const float* xpB = xg + (size_t)(t + 1) * BATCH * GATES3 + xoB;
            nxrA = *(const float2*)(xpA);
            nxzA = *(const float2*)(xpA + HID);
            nxnA = *(const float2*)(xpA + 2 * HID);
            nxrB = *(const float2*)(xpB);
            nxzB = *(const float2*)(xpB + HID);
            nxnB = *(const float2*)(xpB + 2 * HID);
        }

        // half-k dot: 3 gates x 2 cols (FFMA2-packed) x 2 batches
        float2 arA = {0,0}, azA = {0,0}, anA = {0,0};
        float2 arB = {0,0}, azB = {0,0}, anB = {0,0};
#pragma unroll 4
        for (int k = 0; k < 256; k += 4) {
            float4 hA = *(const float4*)(h0p + k);     // batch A: h[k..k+3]
            float4 hB = *(const float4*)(h1p + k);     // batch B
            float4 r01 = *(const float4*)(wr + k * 2);       // (r[c0,k],r[c1,k],r[c0,k+1],r[c1,k+1])
            float4 r23 = *(const float4*)(wr + k * 2 + 4);
            float4 z01 = *(const float4*)(wz + k * 2);
            float4 z23 = *(const float4*)(wz + k * 2 + 4);
            float4 n01 = *(const float4*)(wn + k * 2);
            float4 n23 = *(const float4*)(wn + k * 2 + 4);
            float2 w0, w1, w2, w3;
            // r gate
            w0 = make_float2(r01.x, r01.y); w1 = make_float2(r01.z, r01.w);
            w2 = make_float2(r23.x, r23.y); w3 = make_float2(r23.z, r23.w);
            arA = ffma2(w0, make_float2(hA.x, hA.x), arA);
            arA = ffma2(w1, make_float2(hA.y, hA.y), arA);
            arA = ffma2(w2, make_float2(hA.z, hA.z), arA);
            arA = ffma2(w3, make_float2(hA.w, hA.w), arA);
            arB = ffma2(w0, make_float2(hB.x, hB.x), arB);
            arB = ffma2(w1, make_float2(hB.y, hB.y), arB);
            arB = ffma2(w2, make_float2(hB.z, hB.z), arB);
            arB = ffma2(w3, make_float2(hB.w, hB.w), arB);
            // z gate
            w0 = make_float2(z01.x, z01.y); w1 = make_float2(z01.z, z01.w);
            w2 = make_float2(z23.x, z23.y); w3 = make_float2(z23.z, z23.w);
            azA = ffma2(w0, make_float2(hA.x, hA.x), azA);
            azA = ffma2(w1, make_float2(hA.y, hA.y), azA);
            azA = ffma2(w2, make_float2(hA.z, hA.z), azA);
            azA = ffma2(w3, make_float2(hA.w, hA.w), azA);
            azB = ffma2(w0, make_float2(hB.x, hB.x), azB);
            azB = ffma2(w1, make_float2(hB.y, hB.y), azB);
            azB = ffma2(w2, make_float2(hB.z, hB.z), azB);
            azB = ffma2(w3, make_float2(hB.w, hB.w), azB);
            // n gate
            w0 = make_float2(n01.x, n01.y); w1 = make_float2(n01.z, n01.w);
            w2 = make_float2(n23.x, n23.y); w3 = make_float2(n23.z, n23.w);
            anA = ffma2(w0, make_float2(hA.x, hA.x), anA);
            anA = ffma2(w1, make_float2(hA.y, hA.y), anA);
            anA = ffma2(w2, make_float2(hA.z, hA.z), anA);
            anA = ffma2(w3, make_float2(hA.w, hA.w), anA);
            anB = ffma2(w0, make_float2(hB.x, hB.x), anB);
            anB = ffma2(w1, make_float2(hB.y, hB.y), anB);
            anB = ffma2(w2, make_float2(hB.z, hB.z), anB);
            anB = ffma2(w3, make_float2(hB.w, hB.w), anB);
        }

        // cross-k-half reduction: partner = lane^1 (same warp)
        arA.x += __shfl_xor_sync(0xffffffffu, arA.x, 1);
        arA.y += __shfl_xor_sync(0xffffffffu, arA.y, 1);
        azA.x += __shfl_xor_sync(0xffffffffu, azA.x, 1);
        azA.y += __shfl_xor_sync(0xffffffffu, azA.y, 1);
        anA.x += __shfl_xor_sync(0xffffffffu, anA.x, 1);
        anA.y += __shfl_xor_sync(0xffffffffu, anA.y, 1);
        arB.x += __shfl_xor_sync(0xffffffffu, arB.x, 1);
        arB.y += __shfl_xor_sync(0xffffffffu, arB.y, 1);
        azB.x += __shfl_xor_sync(0xffffffffu, azB.x, 1);
        azB.y += __shfl_xor_sync(0xffffffffu, azB.y, 1);
        anB.x += __shfl_xor_sync(0xffffffffu, anB.x, 1);
        anB.y += __shfl_xor_sync(0xffffffffu, anB.y, 1);

        if (kk == 0) {
            // finalize 4 h values (2 cols x 2 batches)
            float rAx = fast_sigmoid(xrA.x + arA.x + bhr.x);
            float rAy = fast_sigmoid(xrA.y + arA.y + bhr.y);
            float zAx = fast_sigmoid(xzA.x + azA.x + bhz.x);
            float zAy = fast_sigmoid(xzA.y + azA.y + bhz.y);
            float nAx = fast_tanh(xnA.x + rAx * (anA.x + bhn.x));
            float nAy = fast_tanh(xnA.y + rAy * (anA.y + bhn.y));
            hpA.x = (1.f - zAx) * nAx + zAx * hpA.x;
            hpA.y = (1.f - zAy) * nAy + zAy * hpA.y;

            float rBx = fast_sigmoid(xrB.x + arB.x + bhr.x);
            float rBy = fast_sigmoid(xrB.y + arB.y + bhr.y);
            float zBx = fast_sigmoid(xzB.x + azB.x + bhz.x);
            float zBy = fast_sigmoid(xzB.y + azB.y + bhz.y);
            float nBx = fast_tanh(xnB.x + rBx * (anB.x + bhn.x));
            float nBy = fast_tanh(xnB.y + rBy * (anB.y + bhn.y));
            hpB.x = (1.f - zBx) * nBx + zBx * hpB.x;
            hpB.y = (1.f - zBy) * nBy + zBy * hpB.y;

            // publish h to L2 FIRST (critical path for remote blocks)
            float* base = g_hx + (size_t)((t + 1) & 1) * BATCH * HID;
            asm volatile("st.global.cg.v2.f32 [%0], {%1, %2};"
                         :: "l"(base + (size_t)bA * HID + jj), "f"(hpA.x), "f"(hpA.y) : "memory");
            asm volatile("st.global.cg.v2.f32 [%0], {%1, %2};"
                         :: "l"(base + (size_t)bB * HID + jj), "f"(hpB.x), "f"(hpB.y) : "memory");
        }
        __syncthreads();
        if (tid == 0 && t < T_STEPS - 1) {
            __threadfence();
            asm volatile("st.global.cg.u32 [%0], %1;"
                         :: "l"(&g_flags[bid]), "r"((unsigned)(t + 1)) : "memory");
        }

        if (kk == 0) {
            // own-slice shortcut into smem (post-sync: safe vs this step's reads)
            *(float2*)(hs + (bq * 2) * HR + own_off)     = hpA;
            *(float2*)(hs + (bq * 2 + 1) * HR + own_off) = hpB;

            // off critical path: y store, hn store
            *(float2*)(y + ((size_t)t * BATCH + bA) * HID + jj) = hpA;
            *(float2*)(y + ((size_t)t * BATCH + bB) * HID + jj) = hpB;
            if (t == T_STEPS - 1) {
                *(float2*)(hn_out + (size_t)bA * HID + jj) = hpA;
                *(float2*)(hn_out + (size_t)bB * HID + jj) = hpB;
            }
            xrA = nxrA; xzA = nxzA; xnA = nxnA;
            xrB = nxrB; xzB = nxzB; xnB = nxnB;
        }
    }

    // end-of-launch: group gen-barrier (replay-safe), reset own flag
    __syncthreads();
    if (tid == 0) {
        unsigned gen = g_end_gen[grp];
        __threadfence();
        if (atomicAdd(&g_end_cnt[grp], 1u) == 15u) {
            g_end_cnt[grp] = 0u;
            __threadfence();
            g_end_gen[grp] = gen + 1u;
        } else {
            while (g_end_gen[grp] == gen) { __nanosleep(32); }
        }
        g_flags[bid] = 0u;
        __threadfence();
    }
}

// ---------------- launch ----------------
extern "C" void kernel_launch(void* const* d_in, const int* in_sizes, int n_in,
                              void* d_out, int out_size) {
    const float* x    = (const float*)d_in[0];
    const float* Wih0 = (const float*)d_in[1];
    const float* Whh0 = (const float*)d_in[2];
    const float* bih0 = (const float*)d_in[3];
    const float* bhh0 = (const float*)d_in[4];
    const float* Wih1 = (const float*)d_in[5];
    const float* Whh1 = (const float*)d_in[6];
    const float* bih1 = (const float*)d_in[7];
    const float* bhh1 = (const float*)d_in[8];

    float* out = (float*)d_out;
    float* y1  = out;
    float* hn0 = out + (size_t)T_STEPS * BATCH * HID;
    float* hn1 = hn0 + BATCH * HID;

    float *xg, *y0;
    cudaGetSymbolAddress((void**)&xg, g_xg);
    cudaGetSymbolAddress((void**)&y0, g_y0);

    const int rec_smem = (48 * WROWF + 8 * HR) * 4;  // 216,192 B
    cudaFuncSetAttribute(gru_rec_kernel, cudaFuncAttributeMaxDynamicSharedMemorySize, rec_smem);

    dim3 ggrid(12, 256);

    gemm_bias_kernel<<<ggrid, 256>>>(x, Wih0, bih0, xg, 256);
    gru_rec_kernel<<<NB_REC, NT_REC, rec_smem>>>(xg, Whh0, bhh0, y0, hn0);
    gemm_bias_kernel<<<ggrid, 256>>>(y0, Wih1, bih1, xg, 512);
    gru_rec_kernel<<<NB_REC, NT_REC, rec_smem>>>(xg, Whh1, bhh1, y1, hn1);
}

// round 17
// speedup vs baseline: 1.2601x; 1.0369x over previous
#include <cuda_runtime.h>

#define T_STEPS 512
#define BATCH   64
#define HID     512
#define GATES3  1536
#define NB_REC  128
#define NT_REC  128
#define WROWF   1040   // W row stride in floats (2*520; k-half offset 520, 16B-aligned)
#define KHOFF   520    // k-half offset within a W row
#define HR      516    // h row stride in floats (k-half offset 260)

// ---------------- scratch (static device allocations; no cudaMalloc) ----------------
__device__ float g_xg[(size_t)T_STEPS * BATCH * GATES3]; // precomputed input gates
__device__ float g_y0[(size_t)T_STEPS * BATCH * HID];    // layer-0 output
__device__ float g_hx[2 * BATCH * HID];                  // ping-pong h exchange [parity][b][j]
__device__ unsigned g_flags[NB_REC];                     // per-block step flags
__device__ unsigned g_end_cnt[8];
__device__ volatile unsigned g_end_gen[8];

// ---------------- packed fp32x2 FMA (Blackwell FFMA2) ----------------
__device__ __forceinline__ float2 ffma2(float2 a, float2 b, float2 c) {
    float2 d;
    asm("fma.rn.f32x2 %0, %1, %2, %3;"
        : "=l"(reinterpret_cast<unsigned long long&>(d))
        : "l"(reinterpret_cast<unsigned long long&>(a)),
          "l"(reinterpret_cast<unsigned long long&>(b)),
          "l"(reinterpret_cast<unsigned long long&>(c)));
    return d;
}

__device__ __forceinline__ float fast_sigmoid(float x) {
    return __fdividef(1.f, 1.f + __expf(-x));
}
__device__ __forceinline__ float fast_tanh(float x) {
    float r;
    asm("tanh.approx.f32 %0, %1;" : "=f"(r) : "f"(x));
    return r;
}

// ---------------- GEMM: out[M,N] = A[M,K] * W[N,K]^T + bias ----------------
// 128x128 tile, BK=16, DOUBLE-BUFFERED smem: 1 sync/tile, gmem overlapped with FMA.
__global__ void __launch_bounds__(256) gemm_bias_kernel(
    const float* __restrict__ A, const float* __restrict__ W,
    const float* __restrict__ bias, float* __restrict__ out, int K)
{
    __shared__ float As[2][16 * 132];
    __shared__ float Bs[2][16 * 132];

    const int tid = threadIdx.x;
    const int m0 = blockIdx.y * 128;
    const int n0 = blockIdx.x * 128;
    const int tm = tid >> 4;
    const int tn = tid & 15;

    // staging coordinates (2 chunks of 256 threads cover 512 float4 per matrix)
    int row_[2], c4_[2];
#pragma unroll
    for (int u = 0; u < 2; ++u) {
        int s = tid + u * 256;
        row_[u] = s >> 2;
        c4_[u]  = s & 3;
    }

    float2 c2[8][4];
#pragma unroll
    for (int i = 0; i < 8; ++i)
#pragma unroll
        for (int p = 0; p < 4; ++p) c2[i][p] = make_float2(0.f, 0.f);

    float4 ra[2], rb[2];
    // preload tile 0 -> regs -> buffer 0
#pragma unroll
    for (int u = 0; u < 2; ++u) {
        ra[u] = *(const float4*)(A + (size_t)(m0 + row_[u]) * K + c4_[u] * 4);
        rb[u] = *(const float4*)(W + (size_t)(n0 + row_[u]) * K + c4_[u] * 4);
    }
#pragma unroll
    for (int u = 0; u < 2; ++u) {
        int row = row_[u], c4 = c4_[u];
        As[0][(c4 * 4 + 0) * 132 + row] = ra[u].x;
        As[0][(c4 * 4 + 1) * 132 + row] = ra[u].y;
        As[0][(c4 * 4 + 2) * 132 + row] = ra[u].z;
        As[0][(c4 * 4 + 3) * 132 + row] = ra[u].w;
        Bs[0][(c4 * 4 + 0) * 132 + row] = rb[u].x;
        Bs[0][(c4 * 4 + 1) * 132 + row] = rb[u].y;
        Bs[0][(c4 * 4 + 2) * 132 + row] = rb[u].z;
        Bs[0][(c4 * 4 + 3) * 132 + row] = rb[u].w;
    }
    __syncthreads();

    int cur = 0;
    for (int kt = 0; kt < K; kt += 16) {
        const bool has_next = (kt + 16 < K);
        // issue next tile's gmem loads (land during compute below)
        if (has_next) {
#pragma unroll
            for (int u = 0; u < 2; ++u) {
                ra[u] = *(const float4*)(A + (size_t)(m0 + row_[u]) * K + kt + 16 + c4_[u] * 4);
                rb[u] = *(const float4*)(W + (size_t)(n0 + row_[u]) * K + kt + 16 + c4_[u] * 4);
            }
        }

        const float* Ac = As[cur];
        const float* Bc = Bs[cur];
#pragma unroll
        for (int kb = 0; kb < 16; ++kb) {
            float4 a0 = *(const float4*)(Ac + kb * 132 + tm * 8);
            float4 a1 = *(const float4*)(Ac + kb * 132 + tm * 8 + 4);
            float4 b0 = *(const float4*)(Bc + kb * 132 + tn * 8);
            float4 b1 = *(const float4*)(Bc + kb * 132 + tn * 8 + 4);
            float av[8] = {a0.x, a0.y, a0.z, a0.w, a1.x, a1.y, a1.z, a1.w};
            float2 bp[4] = {make_float2(b0.x, b0.y), make_float2(b0.z, b0.w),
                            make_float2(b1.x, b1.y), make_float2(b1.z, b1.w)};
#pragma unroll
            for (int i = 0; i < 8; ++i) {
                float2 as = make_float2(av[i], av[i]);
#pragma unroll
                for (int p = 0; p < 4; ++p) c2[i][p] = ffma2(as, bp[p], c2[i][p]);
            }
        }

        // commit staged regs to the other buffer (read last in the PREVIOUS iter)
        if (has_next) {
            float* An = As[cur ^ 1];
            float* Bn = Bs[cur ^ 1];
#pragma unroll
            for (int u = 0; u < 2; ++u) {
                int row = row_[u], c4 = c4_[u];
                An[(c4 * 4 + 0) * 132 + row] = ra[u].x;
                An[(c4 * 4 + 1) * 132 + row] = ra[u].y;
                An[(c4 * 4 + 2) * 132 + row] = ra[u].z;
                An[(c4 * 4 + 3) * 132 + row] = ra[u].w;
                Bn[(c4 * 4 + 0) * 132 + row] = rb[u].x;
                Bn[(c4 * 4 + 1) * 132 + row] = rb[u].y;
                Bn[(c4 * 4 + 2) * 132 + row] = rb[u].z;
                Bn[(c4 * 4 + 3) * 132 + row] = rb[u].w;
            }
            __syncthreads();
        }
        cur ^= 1;
    }

    const float4 bb0 = *(const float4*)(bias + n0 + tn * 8);
    const float4 bb1 = *(const float4*)(bias + n0 + tn * 8 + 4);
#pragma unroll
    for (int i = 0; i < 8; ++i) {
        int m = m0 + tm * 8 + i;
        float4 o0 = make_float4(c2[i][0].x + bb0.x, c2[i][0].y + bb0.y,
                                c2[i][1].x + bb0.z, c2[i][1].y + bb0.w);
        float4 o1 = make_float4(c2[i][2].x + bb1.x, c2[i][2].y + bb1.y,
                                c2[i][3].x + bb1.z, c2[i][3].y + bb1.w);
        float* dst = out + (size_t)m * GATES3 + n0 + tn * 8;
        *(float4*)(dst)     = o0;
        *(float4*)(dst + 4) = o1;
    }
}

// ---------------- persistent GRU recurrence (R13 champion, byte-identical) ----------
__global__ void __launch_bounds__(NT_REC, 1) gru_rec_kernel(
    const float* __restrict__ xg, const float* __restrict__ Whh,
    const float* __restrict__ bhh, float* __restrict__ y,
    float* __restrict__ hn_out)
{
    extern __shared__ float smem[];
    float* Ws = smem;                  // 48 rows (g*16+cp) x 1040 floats (col-pair interleaved)
    float* hs = smem + 48 * WROWF;     // 8 rows (batch) x 516 floats (k-half at +260)

    const int tid = threadIdx.x;
    const int bid = blockIdx.x;
    const int cg  = bid & 15;
    const int grp = bid >> 4;
    const int j0  = cg * 32;
    const int b0  = grp * 8;
    const int cp  = tid >> 3;          // 0..15
    const int bq  = (tid >> 1) & 3;    // 0..3
    const int kk  = tid & 1;           // 0..1
    const int jj  = j0 + cp * 2;
    const int bA  = b0 + bq * 2;
    const int bB  = bA + 1;

    for (int idx = tid; idx < 96 * 512; idx += NT_REC) {
        int row = idx >> 9;
        int k   = idx & 511;
        int g   = row >> 5;
        int cc  = row & 31;
        int cpp = cc >> 1;
        int c   = cc & 1;
        int kh  = k >> 8;
        int kl  = k & 255;
        Ws[(g * 16 + cpp) * WROWF + kh * KHOFF + kl * 2 + c] =
            Whh[(size_t)(g * HID + j0 + cc) * HID + k];
    }
    for (int idx = tid; idx < 8 * HR; idx += NT_REC) hs[idx] = 0.f;

    const float2 bhr = *(const float2*)(bhh + jj);
    const float2 bhz = *(const float2*)(bhh + HID + jj);
    const float2 bhn = *(const float2*)(bhh + 2 * HID + jj);

    const float* wr = Ws + cp * WROWF + kk * KHOFF;
    const float* wz = wr + 16 * WROWF;
    const float* wn = wr + 32 * WROWF;
    const float* h0p = hs + (bq * 2) * HR + kk * 260;
    const float* h1p = h0p + HR;

    const size_t xoA = (size_t)bA * GATES3 + jj;
    const size_t xoB = (size_t)bB * GATES3 + jj;
    float2 xrA = {0,0}, xzA = {0,0}, xnA = {0,0};
    float2 xrB = {0,0}, xzB = {0,0}, xnB = {0,0};
    if (kk == 0) {
        xrA = *(const float2*)(xg + xoA);
        xzA = *(const float2*)(xg + xoA + HID);
        xnA = *(const float2*)(xg + xoA + 2 * HID);
        xrB = *(const float2*)(xg + xoB);
        xzB = *(const float2*)(xg + xoB + HID);
        xnB = *(const float2*)(xg + xoB + 2 * HID);
    }

    float2 hpA = {0,0}, hpB = {0,0};
    const int own_off = jj + ((cg >= 8) ? 4 : 0);
    __syncthreads();

    for (int t = 0; t < T_STEPS; ++t) {
        if (t > 0) {
            if (tid < 16 && tid != cg) {
                const unsigned* fp = &g_flags[grp * 16 + tid];
                unsigned v;
                do {
                    asm volatile("ld.acquire.gpu.global.u32 %0, [%1];" : "=r"(v) : "l"(fp));
                } while (v < (unsigned)t);
            }
            __syncthreads();
            const float* hsrc = g_hx + (size_t)(t & 1) * BATCH * HID;
#pragma unroll
            for (int i = 0; i < 8; ++i) {
                int idx = tid + i * NT_REC;
                int bb  = idx >> 7;
                int kq  = idx & 127;
                if ((kq >> 3) != cg) {
                    float4 hv = __ldcg((const float4*)(hsrc + (size_t)(b0 + bb) * HID + kq * 4));
                    *(float4*)(hs + bb * HR + ((kq >= 64) ? 4 : 0) + kq * 4) = hv;
                }
            }
            __syncthreads();
        }

        float2 nxrA = {0,0}, nxzA = {0,0}, nxnA = {0,0};
        float2 nxrB = {0,0}, nxzB = {0,0}, nxnB = {0,0};
        if (kk == 0 && t + 1 < T_STEPS) {
            const float* xpA = xg + (size_t)(t + 1) * BATCH * GATES3 + xoA;
            const float* xpB = xg + (size_t)(t + 1) * BATCH * GATES3 + xoB;
            nxrA = *(const float2*)(xpA);
            nxzA = *(const float2*)(xpA + HID);
            nxnA = *(const float2*)(xpA + 2 * HID);
            nxrB = *(const float2*)(xpB);
            nxzB = *(const float2*)(xpB + HID);
            nxnB = *(const float2*)(xpB + 2 * HID);
        }

        float2 arA = {0,0}, azA = {0,0}, anA = {0,0};
        float2 arB = {0,0}, azB = {0,0}, anB = {0,0};
#pragma unroll 4
        for (int k = 0; k < 256; k += 4) {
            float4 hA = *(const float4*)(h0p + k);
            float4 hB = *(const float4*)(h1p + k);
            float4 r01 = *(const float4*)(wr + k * 2);
            float4 r23 = *(const float4*)(wr + k * 2 + 4);
            float4 z01 = *(const float4*)(wz + k * 2);
            float4 z23 = *(const float4*)(wz + k * 2 + 4);
            float4 n01 = *(const float4*)(wn + k * 2);
            float4 n23 = *(const float4*)(wn + k * 2 + 4);
            float2 w0, w1, w2, w3;
            w0 = make_float2(r01.x, r01.y); w1 = make_float2(r01.z, r01.w);
            w2 = make_float2(r23.x, r23.y); w3 = make_float2(r23.z, r23.w);
            arA = ffma2(w0, make_float2(hA.x, hA.x), arA);
            arA = ffma2(w1, make_float2(hA.y, hA.y), arA);
            arA = ffma2(w2, make_float2(hA.z, hA.z), arA);
            arA = ffma2(w3, make_float2(hA.w, hA.w), arA);
            arB = ffma2(w0, make_float2(hB.x, hB.x), arB);
            arB = ffma2(w1, make_float2(hB.y, hB.y), arB);
            arB = ffma2(w2, make_float2(hB.z, hB.z), arB);
            arB = ffma2(w3, make_float2(hB.w, hB.w), arB);
            w0 = make_float2(z01.x, z01.y); w1 = make_float2(z01.z, z01.w);
            w2 = make_float2(z23.x, z23.y); w3 = make_float2(z23.z, z23.w);
            azA = ffma2(w0, make_float2(hA.x, hA.x), azA);
            azA = ffma2(w1, make_float2(hA.y, hA.y), azA);
            azA = ffma2(w2, make_float2(hA.z, hA.z), azA);
            azA = ffma2(w3, make_float2(hA.w, hA.w), azA);
            azB = ffma2(w0, make_float2(hB.x, hB.x), azB);
            azB = ffma2(w1, make_float2(hB.y, hB.y), azB);
            azB = ffma2(w2, make_float2(hB.z, hB.z), azB);
            azB = ffma2(w3, make_float2(hB.w, hB.w), azB);
            w0 = make_float2(n01.x, n01.y); w1 = make_float2(n01.z, n01.w);
            w2 = make_float2(n23.x, n23.y); w3 = make_float2(n23.z, n23.w);
            anA = ffma2(w0, make_float2(hA.x, hA.x), anA);
            anA = ffma2(w1, make_float2(hA.y, hA.y), anA);
            anA = ffma2(w2, make_float2(hA.z, hA.z), anA);
            anA = ffma2(w3, make_float2(hA.w, hA.w), anA);
            anB = ffma2(w0, make_float2(hB.x, hB.x), anB);
            anB = ffma2(w1, make_float2(hB.y, hB.y), anB);
            anB = ffma2(w2, make_float2(hB.z, hB.z), anB);
            anB = ffma2(w3, make_float2(hB.w, hB.w), anB);
        }

        arA.x += __shfl_xor_sync(0xffffffffu, arA.x, 1);
        arA.y += __shfl_xor_sync(0xffffffffu, arA.y, 1);
        azA.x += __shfl_xor_sync(0xffffffffu, azA.x, 1);
        azA.y += __shfl_xor_sync(0xffffffffu, azA.y, 1);
        anA.x += __shfl_xor_sync(0xffffffffu, anA.x, 1);
        anA.y += __shfl_xor_sync(0xffffffffu, anA.y, 1);
        arB.x += __shfl_xor_sync(0xffffffffu, arB.x, 1);
        arB.y += __shfl_xor_sync(0xffffffffu, arB.y, 1);
        azB.x += __shfl_xor_sync(0xffffffffu, azB.x, 1);
        azB.y += __shfl_xor_sync(0xffffffffu, azB.y, 1);
        anB.x += __shfl_xor_sync(0xffffffffu, anB.x, 1);
        anB.y += __shfl_xor_sync(0xffffffffu, anB.y, 1);

        if (kk == 0) {
            float rAx = fast_sigmoid(xrA.x + arA.x + bhr.x);
            float rAy = fast_sigmoid(xrA.y + arA.y + bhr.y);
            float zAx = fast_sigmoid(xzA.x + azA.x + bhz.x);
            float zAy = fast_sigmoid(xzA.y + azA.y + bhz.y);
            float nAx = fast_tanh(xnA.x + rAx * (anA.x + bhn.x));
            float nAy = fast_tanh(xnA.y + rAy * (anA.y + bhn.y));
            hpA.x = (1.f - zAx) * nAx + zAx * hpA.x;
            hpA.y = (1.f - zAy) * nAy + zAy * hpA.y;

            float rBx = fast_sigmoid(xrB.x + arB.x + bhr.x);
            float rBy = fast_sigmoid(xrB.y + arB.y + bhr.y);
            float zBx = fast_sigmoid(xzB.x + azB.x + bhz.x);
            float zBy = fast_sigmoid(xzB.y + azB.y + bhz.y);
            float nBx = fast_tanh(xnB.x + rBx * (anB.x + bhn.x));
            float nBy = fast_tanh(xnB.y + rBy * (anB.y + bhn.y));
            hpB.x = (1.f - zBx) * nBx + zBx * hpB.x;
            hpB.y = (1.f - zBy) * nBy + zBy * hpB.y;

            float* base = g_hx + (size_t)((t + 1) & 1) * BATCH * HID;
            asm volatile("st.global.cg.v2.f32 [%0], {%1, %2};"
                         :: "l"(base + (size_t)bA * HID + jj), "f"(hpA.x), "f"(hpA.y) : "memory");
            asm volatile("st.global.cg.v2.f32 [%0], {%1, %2};"
                         :: "l"(base + (size_t)bB * HID + jj), "f"(hpB.x), "f"(hpB.y) : "memory");
        }
        __syncthreads();
        if (tid == 0 && t < T_STEPS - 1) {
            __threadfence();
            asm volatile("st.global.cg.u32 [%0], %1;"
                         :: "l"(&g_flags[bid]), "r"((unsigned)(t + 1)) : "memory");
        }

        if (kk == 0) {
            *(float2*)(hs + (bq * 2) * HR + own_off)     = hpA;
            *(float2*)(hs + (bq * 2 + 1) * HR + own_off) = hpB;

            *(float2*)(y + ((size_t)t * BATCH + bA) * HID + jj) = hpA;
            *(float2*)(y + ((size_t)t * BATCH + bB) * HID + jj) = hpB;
            if (t == T_STEPS - 1) {
                *(float2*)(hn_out + (size_t)bA * HID + jj) = hpA;
                *(float2*)(hn_out + (size_t)bB * HID + jj) = hpB;
            }
            xrA = nxrA; xzA = nxzA; xnA = nxnA;
            xrB = nxrB; xzB = nxzB; xnB = nxnB;
        }
    }

    __syncthreads();
    if (tid == 0) {
        unsigned gen = g_end_gen[grp];
        __threadfence();
        if (atomicAdd(&g_end_cnt[grp], 1u) == 15u) {
            g_end_cnt[grp] = 0u;
            __threadfence();
            g_end_gen[grp] = gen + 1u;
        } else {
            while (g_end_gen[grp] == gen) { __nanosleep(32); }
        }
        g_flags[bid] = 0u;
        __threadfence();
    }
}

// ---------------- launch ----------------
extern "C" void kernel_launch(void* const* d_in, const int* in_sizes, int n_in,
                              void* d_out, int out_size) {
    const float* x    = (const float*)d_in[0];
    const float* Wih0 = (const float*)d_in[1];
    const float* Whh0 = (const float*)d_in[2];
    const float* bih0 = (const float*)d_in[3];
    const float* bhh0 = (const float*)d_in[4];
    const float* Wih1 = (const float*)d_in[5];
    const float* Whh1 = (const float*)d_in[6];
    const float* bih1 = (const float*)d_in[7];
    const float* bhh1 = (const float*)d_in[8];

    float* out = (float*)d_out;
    float* y1  = out;
    float* hn0 = out + (size_t)T_STEPS * BATCH * HID;
    float* hn1 = hn0 + BATCH * HID;

    float *xg, *y0;
    cudaGetSymbolAddress((void**)&xg, g_xg);
    cudaGetSymbolAddress((void**)&y0, g_y0);

    const int rec_smem = (48 * WROWF + 8 * HR) * 4;  // 216,192 B
    cudaFuncSetAttribute(gru_rec_kernel, cudaFuncAttributeMaxDynamicSharedMemorySize, rec_smem);

    dim3 ggrid(12, 256);

    gemm_bias_kernel<<<ggrid, 256>>>(x, Wih0, bih0, xg, 256);
    gru_rec_kernel<<<NB_REC, NT_REC, rec_smem>>>(xg, Whh0, bhh0, y0, hn0);
    gemm_bias_kernel<<<ggrid, 256>>>(y0, Wih1, bih1, xg, 512);
    gru_rec_kernel<<<NB_REC, NT_REC, rec_smem>>>(xg, Whh1, bhh1, y1, hn1);
}